// round 12
// baseline (speedup 1.0000x reference)
#include <cuda_runtime.h>
#include <cuda_fp16.h>
#include <math.h>

#define NN    50000
#define FIN   128
#define C1    128
#define HEADS 4
#define HID   32
#define CLS   40
#define EE    800000
#define TOTE  (EE + NN)
#define NEG   0.2f
#define SCANB 196            // ceil(NN/256)

// ---------------- scratch ----------------
__device__ __half g_h1h[NN * C1];
__device__ float  g_out1[NN * C1];
__device__ __half g_h2h[NN * CLS];
__device__ float  g_als1[NN * HEADS];
__device__ float  g_ald1[NN * HEADS];
__device__ float  g_als2[NN];
__device__ float  g_ald2[NN];
__device__ int    g_cnt [NN];
__device__ int    g_rowptr[NN + 1];
__device__ int    g_csr_src[TOTE];
__device__ int    g_bsum[256];
__device__ int    g_boff[256];

__device__ __forceinline__ float lrelu(float x) { return x > 0.f ? x : NEG * x; }

__device__ __forceinline__ unsigned long long pk2(float a, float b) {
    unsigned long long r;
    asm("mov.b64 %0, {%1, %2};" : "=l"(r)
        : "r"(__float_as_uint(a)), "r"(__float_as_uint(b)));
    return r;
}
__device__ __forceinline__ void fma2(unsigned long long& d,
                                     unsigned long long a, unsigned long long b) {
    asm("fma.rn.f32x2 %0, %1, %2, %0;" : "+l"(d) : "l"(a), "l"(b));
}
__device__ __forceinline__ float2 up2(unsigned long long p) {
    unsigned int lo, hi;
    asm("mov.b64 {%0, %1}, %2;" : "=r"(lo), "=r"(hi) : "l"(p));
    return make_float2(__uint_as_float(lo), __uint_as_float(hi));
}
__device__ __forceinline__ float2 h2f(unsigned int u) {
    __half2 h = *reinterpret_cast<__half2*>(&u);
    return __half22float2(h);
}
__device__ __forceinline__ unsigned int f2h(float a, float b) {
    __half2 h = __float22half2_rn(make_float2(a, b));
    return *reinterpret_cast<unsigned int*>(&h);
}
__device__ __forceinline__ void mma_tf32(float* c, const unsigned* a, const unsigned* b) {
    asm volatile(
        "mma.sync.aligned.m16n8k8.row.col.f32.tf32.tf32.f32 "
        "{%0,%1,%2,%3}, {%4,%5,%6,%7}, {%8,%9}, {%0,%1,%2,%3};"
        : "+f"(c[0]), "+f"(c[1]), "+f"(c[2]), "+f"(c[3])
        : "r"(a[0]), "r"(a[1]), "r"(a[2]), "r"(a[3]), "r"(b[0]), "r"(b[1]));
}
__device__ __forceinline__ void cpa16(void* dst_smem, const void* src, int nbytes) {
    unsigned d = (unsigned)__cvta_generic_to_shared(dst_smem);
    asm volatile("cp.async.cg.shared.global [%0], [%1], 16, %2;"
                 :: "r"(d), "l"(src), "r"(nbytes) : "memory");
}
#define CP_COMMIT() asm volatile("cp.async.commit_group;" ::: "memory")
#define CP_WAIT(n)  asm volatile("cp.async.wait_group %0;" :: "n"(n) : "memory")

// ---------------- CSR build ----------------
__global__ void hist_kernel(const int* __restrict__ ei) {
    int q = (blockIdx.x * blockDim.x + threadIdx.x) * 8;
    if (q >= TOTE) return;
    if (q + 8 <= EE) {
        int4 a = *(const int4*)&ei[EE + q];
        int4 b = *(const int4*)&ei[EE + q + 4];
        asm volatile("red.global.add.u32 [%0], %1;" :: "l"(&g_cnt[a.x]), "r"(1) : "memory");
        asm volatile("red.global.add.u32 [%0], %1;" :: "l"(&g_cnt[a.y]), "r"(1) : "memory");
        asm volatile("red.global.add.u32 [%0], %1;" :: "l"(&g_cnt[a.z]), "r"(1) : "memory");
        asm volatile("red.global.add.u32 [%0], %1;" :: "l"(&g_cnt[a.w]), "r"(1) : "memory");
        asm volatile("red.global.add.u32 [%0], %1;" :: "l"(&g_cnt[b.x]), "r"(1) : "memory");
        asm volatile("red.global.add.u32 [%0], %1;" :: "l"(&g_cnt[b.y]), "r"(1) : "memory");
        asm volatile("red.global.add.u32 [%0], %1;" :: "l"(&g_cnt[b.z]), "r"(1) : "memory");
        asm volatile("red.global.add.u32 [%0], %1;" :: "l"(&g_cnt[b.w]), "r"(1) : "memory");
    } else {
        for (int j = 0; j < 8 && q + j < TOTE; j++) {
            int e = q + j;
            int d = (e < EE) ? ei[EE + e] : e - EE;
            asm volatile("red.global.add.u32 [%0], %1;" :: "l"(&g_cnt[d]), "r"(1) : "memory");
        }
    }
}
// blockwise exclusive scan (3 stages)
__global__ void scanA_kernel() {
    __shared__ int sm[256];
    int t = threadIdx.x, i = blockIdx.x * 256 + t;
    int v = (i < NN) ? g_cnt[i] : 0;
    int acc = v;
    sm[t] = acc; __syncthreads();
    for (int off = 1; off < 256; off <<= 1) {
        int u = (t >= off) ? sm[t - off] : 0;
        __syncthreads();
        acc += u; sm[t] = acc;
        __syncthreads();
    }
    if (i < NN) g_rowptr[i] = acc - v;          // local exclusive
    if (t == 255) g_bsum[blockIdx.x] = acc;     // block total
}
__global__ void scanB_kernel() {
    __shared__ int sm[256];
    int t = threadIdx.x;
    int v = (t < SCANB) ? g_bsum[t] : 0;
    int acc = v;
    sm[t] = acc; __syncthreads();
    for (int off = 1; off < 256; off <<= 1) {
        int u = (t >= off) ? sm[t - off] : 0;
        __syncthreads();
        acc += u; sm[t] = acc;
        __syncthreads();
    }
    g_boff[t] = acc - v;                        // exclusive block offset
}
__global__ void scanC_kernel() {
    int t = threadIdx.x, i = blockIdx.x * 256 + t;
    if (i < NN) {
        int r = g_rowptr[i] + g_boff[blockIdx.x];
        g_rowptr[i] = r;
        g_cnt[i] = r;                           // cursor for scatter
    }
    if (i == 0) g_rowptr[NN] = TOTE;
}
__global__ void scatter_kernel(const int* __restrict__ ei) {
    int q = (blockIdx.x * blockDim.x + threadIdx.x) * 8;
    if (q >= TOTE) return;
    if (q + 8 <= EE) {
        int4 sa = *(const int4*)&ei[q];
        int4 sb = *(const int4*)&ei[q + 4];
        int4 da = *(const int4*)&ei[EE + q];
        int4 db = *(const int4*)&ei[EE + q + 4];
        int p0 = atomicAdd(&g_cnt[da.x], 1);
        int p1 = atomicAdd(&g_cnt[da.y], 1);
        int p2 = atomicAdd(&g_cnt[da.z], 1);
        int p3 = atomicAdd(&g_cnt[da.w], 1);
        int p4 = atomicAdd(&g_cnt[db.x], 1);
        int p5 = atomicAdd(&g_cnt[db.y], 1);
        int p6 = atomicAdd(&g_cnt[db.z], 1);
        int p7 = atomicAdd(&g_cnt[db.w], 1);
        g_csr_src[p0] = sa.x; g_csr_src[p1] = sa.y;
        g_csr_src[p2] = sa.z; g_csr_src[p3] = sa.w;
        g_csr_src[p4] = sb.x; g_csr_src[p5] = sb.y;
        g_csr_src[p6] = sb.z; g_csr_src[p7] = sb.w;
    } else {
        for (int j = 0; j < 8 && q + j < TOTE; j++) {
            int e = q + j;
            int s, d;
            if (e < EE) { s = ei[e]; d = ei[EE + e]; } else { s = d = e - EE; }
            int pos = atomicAdd(&g_cnt[d], 1);
            g_csr_src[pos] = s;
        }
    }
}

// ---------------- GEMM1 (tf32, cp.async double-buffered x, W resident) ----------------
// dynamic smem: xs[2][128][36] | ws[128][136] | ps[128][4] | pd[128][4]
#define XS_STR 36
#define WS_STR 136
#define SM_XS(buf)  (sm + (buf) * 128 * XS_STR)
#define SM_WS       (sm + 2 * 128 * XS_STR)
#define SM_PS       (SM_WS + 128 * WS_STR)
#define SM_PD       (SM_PS + 512)
#define GEMM1_SMEM  ((2 * 128 * XS_STR + 128 * WS_STR + 1024) * sizeof(float))

__global__ __launch_bounds__(256, 2) void gemm1_kernel(const float* __restrict__ x,
                                                       const float* __restrict__ W,
                                                       const float* __restrict__ att_s,
                                                       const float* __restrict__ att_d) {
    extern __shared__ float sm[];
    float* ps_s = SM_PS;
    float* pd_s = SM_PD;
    int t = threadIdx.x;
    int row0 = blockIdx.x * 128;
    int w = t >> 5, lane = t & 31;
    int wm = w & 3, wn = w >> 2;
    int q = lane >> 2, rsub = lane & 3;

    if (t < 128) *(float4*)&ps_s[t * 4] = make_float4(0.f, 0.f, 0.f, 0.f);
    else         *(float4*)&pd_s[(t - 128) * 4] = make_float4(0.f, 0.f, 0.f, 0.f);

    // prologue: async-load x tile 0, then all of W
    {
        float* xb = SM_XS(0);
#pragma unroll
        for (int j = 0; j < 4; j++) {
            int idx = t + 256 * j;
            int r = idx >> 3, kq = idx & 7;
            int gr = row0 + r;
            bool val = gr < NN;
            const float* src = x + (val ? gr : 0) * FIN + kq * 4;
            cpa16(&xb[r * XS_STR + kq * 4], src, val ? 16 : 0);
        }
        CP_COMMIT();
        float* wsm = SM_WS;
#pragma unroll
        for (int j = 0; j < 16; j++) {
            int idx = t + 256 * j;
            int kk = idx >> 5, c4 = idx & 31;
            cpa16(&wsm[kk * WS_STR + c4 * 4], &W[kk * C1 + c4 * 4], 16);
        }
        CP_COMMIT();
    }

    float c[2][8][4];
#pragma unroll
    for (int mt = 0; mt < 2; mt++)
#pragma unroll
        for (int nt = 0; nt < 8; nt++)
#pragma unroll
            for (int i = 0; i < 4; i++) c[mt][nt][i] = 0.f;

    float* wsm = SM_WS;
#pragma unroll
    for (int kt = 0; kt < 4; kt++) {
        if (kt < 3) {   // prefetch next x tile
            float* xn = SM_XS((kt + 1) & 1);
            int k0 = (kt + 1) * 32;
#pragma unroll
            for (int j = 0; j < 4; j++) {
                int idx = t + 256 * j;
                int r = idx >> 3, kq = idx & 7;
                int gr = row0 + r;
                bool val = gr < NN;
                const float* src = x + (val ? gr : 0) * FIN + k0 + kq * 4;
                cpa16(&xn[r * XS_STR + kq * 4], src, val ? 16 : 0);
            }
            CP_COMMIT();
            CP_WAIT(1);
        } else {
            CP_WAIT(0);
        }
        __syncthreads();

        float* xb = SM_XS(kt & 1);
        int kg = kt * 32;
#pragma unroll
        for (int ks = 0; ks < 4; ks++) {
            int kb = ks * 8;
            unsigned af[2][4];
#pragma unroll
            for (int mt = 0; mt < 2; mt++) {
                int rb = wm * 32 + mt * 16;
                af[mt][0] = __float_as_uint(xb[(rb + q    ) * XS_STR + kb + rsub    ]);
                af[mt][1] = __float_as_uint(xb[(rb + q + 8) * XS_STR + kb + rsub    ]);
                af[mt][2] = __float_as_uint(xb[(rb + q    ) * XS_STR + kb + rsub + 4]);
                af[mt][3] = __float_as_uint(xb[(rb + q + 8) * XS_STR + kb + rsub + 4]);
            }
            unsigned bf[8][2];
#pragma unroll
            for (int nt = 0; nt < 8; nt++) {
                int col = wn * 64 + nt * 8 + q;
                bf[nt][0] = __float_as_uint(wsm[(kg + kb + rsub    ) * WS_STR + col]);
                bf[nt][1] = __float_as_uint(wsm[(kg + kb + rsub + 4) * WS_STR + col]);
            }
#pragma unroll
            for (int mt = 0; mt < 2; mt++)
#pragma unroll
                for (int nt = 0; nt < 8; nt++)
                    mma_tf32(c[mt][nt], af[mt], bf[nt]);
        }
        __syncthreads();
    }

    // ---- epilogue: store h1 (fp16) + per-head logit partials ----
    float2 asv[8], adv[8];
#pragma unroll
    for (int nt = 0; nt < 8; nt++) {
        int col = wn * 64 + nt * 8 + 2 * rsub;
        asv[nt] = *(const float2*)&att_s[col];
        adv[nt] = *(const float2*)&att_d[col];
    }
#pragma unroll
    for (int mt = 0; mt < 2; mt++) {
        int rloc0 = wm * 32 + mt * 16 + q;
        int rloc1 = rloc0 + 8;
        float psl0 = 0.f, psh0 = 0.f, pdl0 = 0.f, pdh0 = 0.f;
        float psl1 = 0.f, psh1 = 0.f, pdl1 = 0.f, pdh1 = 0.f;
#pragma unroll
        for (int nt = 0; nt < 8; nt++) {
            float c0 = c[mt][nt][0], c1 = c[mt][nt][1];
            float c2 = c[mt][nt][2], c3 = c[mt][nt][3];
            float s0 = c0 * asv[nt].x + c1 * asv[nt].y;
            float d0 = c0 * adv[nt].x + c1 * adv[nt].y;
            float s1 = c2 * asv[nt].x + c3 * asv[nt].y;
            float d1 = c2 * adv[nt].x + c3 * adv[nt].y;
            if (nt < 4) { psl0 += s0; pdl0 += d0; psl1 += s1; pdl1 += d1; }
            else        { psh0 += s0; pdh0 += d0; psh1 += s1; pdh1 += d1; }
            int colg = wn * 64 + nt * 8 + 2 * rsub;
            int gr0 = row0 + rloc0, gr1 = row0 + rloc1;
            if (gr0 < NN) *(unsigned*)&g_h1h[gr0 * C1 + colg] = f2h(c0, c1);
            if (gr1 < NN) *(unsigned*)&g_h1h[gr1 * C1 + colg] = f2h(c2, c3);
        }
#pragma unroll
        for (int o = 1; o < 4; o <<= 1) {
            psl0 += __shfl_down_sync(0xffffffff, psl0, o, 4);
            psh0 += __shfl_down_sync(0xffffffff, psh0, o, 4);
            pdl0 += __shfl_down_sync(0xffffffff, pdl0, o, 4);
            pdh0 += __shfl_down_sync(0xffffffff, pdh0, o, 4);
            psl1 += __shfl_down_sync(0xffffffff, psl1, o, 4);
            psh1 += __shfl_down_sync(0xffffffff, psh1, o, 4);
            pdl1 += __shfl_down_sync(0xffffffff, pdl1, o, 4);
            pdh1 += __shfl_down_sync(0xffffffff, pdh1, o, 4);
        }
        if (rsub == 0) {
            int hlo = wn * 2, hhi = wn * 2 + 1;
            atomicAdd(&ps_s[rloc0 * 4 + hlo], psl0);
            atomicAdd(&ps_s[rloc0 * 4 + hhi], psh0);
            atomicAdd(&pd_s[rloc0 * 4 + hlo], pdl0);
            atomicAdd(&pd_s[rloc0 * 4 + hhi], pdh0);
            atomicAdd(&ps_s[rloc1 * 4 + hlo], psl1);
            atomicAdd(&ps_s[rloc1 * 4 + hhi], psh1);
            atomicAdd(&pd_s[rloc1 * 4 + hlo], pdl1);
            atomicAdd(&pd_s[rloc1 * 4 + hhi], pdh1);
        }
    }
    __syncthreads();
    if (t < 128) {
        int gr = row0 + t;
        if (gr < NN) *(float4*)&g_als1[gr * HEADS] = *(float4*)&ps_s[t * 4];
    } else {
        int rr = t - 128;
        int gr = row0 + rr;
        if (gr < NN) *(float4*)&g_ald1[gr * HEADS] = *(float4*)&pd_s[rr * 4];
    }
}

// ---------------- layer-1 aggregation ----------------
__global__ void agg1_kernel(const float* __restrict__ b1) {
    int gt = blockIdx.x * blockDim.x + threadIdx.x;
    int n = gt >> 5, lane = gt & 31;
    if (n >= NN) return;
    int h = lane >> 3;
    float ald = g_ald1[n * HEADS + h];
    int beg = g_rowptr[n], end = g_rowptr[n + 1];
    float4 acc = make_float4(0.f, 0.f, 0.f, 0.f);
    float den = 0.f;
    int i = beg;
    for (; i + 4 <= end; i += 4) {
        int sA = __ldg(&g_csr_src[i]);
        int sB = __ldg(&g_csr_src[i + 1]);
        int sC = __ldg(&g_csr_src[i + 2]);
        int sD = __ldg(&g_csr_src[i + 3]);
        float aA = __ldg(&g_als1[sA * HEADS + h]);
        float aB = __ldg(&g_als1[sB * HEADS + h]);
        float aC = __ldg(&g_als1[sC * HEADS + h]);
        float aD = __ldg(&g_als1[sD * HEADS + h]);
        uint2 rA = *(const uint2*)&g_h1h[sA * C1 + lane * 4];
        uint2 rB = *(const uint2*)&g_h1h[sB * C1 + lane * 4];
        uint2 rC = *(const uint2*)&g_h1h[sC * C1 + lane * 4];
        uint2 rD = *(const uint2*)&g_h1h[sD * C1 + lane * 4];
        float wA = __expf(lrelu(aA + ald));
        float wB = __expf(lrelu(aB + ald));
        float wC = __expf(lrelu(aC + ald));
        float wD = __expf(lrelu(aD + ald));
        den += (wA + wB) + (wC + wD);
        float2 A0 = h2f(rA.x), A1 = h2f(rA.y);
        float2 B0 = h2f(rB.x), B1 = h2f(rB.y);
        float2 C0 = h2f(rC.x), C1v = h2f(rC.y);
        float2 D0 = h2f(rD.x), D1 = h2f(rD.y);
        acc.x += wA * A0.x + wB * B0.x + wC * C0.x + wD * D0.x;
        acc.y += wA * A0.y + wB * B0.y + wC * C0.y + wD * D0.y;
        acc.z += wA * A1.x + wB * B1.x + wC * C1v.x + wD * D1.x;
        acc.w += wA * A1.y + wB * B1.y + wC * C1v.y + wD * D1.y;
    }
    for (; i < end; i++) {
        int s = __ldg(&g_csr_src[i]);
        float w = __expf(lrelu(__ldg(&g_als1[s * HEADS + h]) + ald));
        den += w;
        uint2 r = *(const uint2*)&g_h1h[s * C1 + lane * 4];
        float2 p0 = h2f(r.x), p1 = h2f(r.y);
        acc.x += w * p0.x; acc.y += w * p0.y;
        acc.z += w * p1.x; acc.w += w * p1.y;
    }
    float inv = 1.f / (den + 1e-16f);
    float4 bb = *(const float4*)&b1[lane * 4];
    float4 o;
    o.x = fmaxf(acc.x * inv + bb.x, 0.f);
    o.y = fmaxf(acc.y * inv + bb.y, 0.f);
    o.z = fmaxf(acc.z * inv + bb.z, 0.f);
    o.w = fmaxf(acc.w * inv + bb.w, 0.f);
    *(float4*)&g_out1[n * C1 + lane * 4] = o;
}

// ---------------- GEMM2 + layer-2 logits ----------------
__global__ __launch_bounds__(256) void l2gemm_kernel(const float* __restrict__ W2,
                                                     const float* __restrict__ as2,
                                                     const float* __restrict__ ad2) {
    __shared__ __align__(16) float W2s[FIN * CLS];
    __shared__ float s2s[CLS], d2s[CLS];
    int t = threadIdx.x;
    for (int i = t; i < FIN * CLS; i += 256) W2s[i] = W2[i];
    if (t < CLS) { s2s[t] = as2[t]; d2s[t] = ad2[t]; }
    __syncthreads();

    int n = blockIdx.x * blockDim.x + t;
    if (n >= NN) return;
    unsigned long long acc[20];
#pragma unroll
    for (int c = 0; c < 20; c++) acc[c] = 0ULL;

    for (int k = 0; k < FIN; k += 4) {
        float4 r4 = *(const float4*)&g_out1[n * FIN + k];
        float rv[4] = {r4.x, r4.y, r4.z, r4.w};
#pragma unroll
        for (int qq = 0; qq < 4; qq++) {
            unsigned long long rp = pk2(rv[qq], rv[qq]);
            const float* wrow = &W2s[(k + qq) * CLS];
#pragma unroll
            for (int c4 = 0; c4 < 10; c4++) {
                ulonglong2 wp = *(const ulonglong2*)&wrow[c4 * 4];
                fma2(acc[c4 * 2 + 0], rp, wp.x);
                fma2(acc[c4 * 2 + 1], rp, wp.y);
            }
        }
    }
    float ls = 0.f, ld = 0.f;
    unsigned int hp[20];
#pragma unroll
    for (int c2 = 0; c2 < 20; c2++) {
        float2 v = up2(acc[c2]);
        hp[c2] = f2h(v.x, v.y);
        ls += v.x * s2s[c2 * 2] + v.y * s2s[c2 * 2 + 1];
        ld += v.x * d2s[c2 * 2] + v.y * d2s[c2 * 2 + 1];
    }
    uint4* dst = (uint4*)&g_h2h[n * CLS];
#pragma unroll
    for (int j = 0; j < 5; j++) {
        uint4 u;
        u.x = hp[j * 4 + 0]; u.y = hp[j * 4 + 1];
        u.z = hp[j * 4 + 2]; u.w = hp[j * 4 + 3];
        dst[j] = u;
    }
    g_als2[n] = ls;
    g_ald2[n] = ld;
}

// ---------------- layer-2 aggregation + bias + log_softmax ----------------
__global__ void agg2_kernel(const float* __restrict__ b2, float* __restrict__ out) {
    int gt = blockIdx.x * blockDim.x + threadIdx.x;
    int n = gt >> 5, lane = gt & 31;
    if (n >= NN) return;
    float ald = g_ald2[n];
    int beg = g_rowptr[n], end = g_rowptr[n + 1];
    bool act = lane < 10;
    float4 acc = make_float4(0.f, 0.f, 0.f, 0.f);
    float den = 0.f;
    int i = beg;
    for (; i + 4 <= end; i += 4) {
        int sA = __ldg(&g_csr_src[i]);
        int sB = __ldg(&g_csr_src[i + 1]);
        int sC = __ldg(&g_csr_src[i + 2]);
        int sD = __ldg(&g_csr_src[i + 3]);
        float aA = __ldg(&g_als2[sA]);
        float aB = __ldg(&g_als2[sB]);
        float aC = __ldg(&g_als2[sC]);
        float aD = __ldg(&g_als2[sD]);
        uint2 rA = make_uint2(0u, 0u), rB = rA, rC = rA, rD = rA;
        if (act) {
            rA = *(const uint2*)&g_h2h[sA * CLS + lane * 4];
            rB = *(const uint2*)&g_h2h[sB * CLS + lane * 4];
            rC = *(const uint2*)&g_h2h[sC * CLS + lane * 4];
            rD = *(const uint2*)&g_h2h[sD * CLS + lane * 4];
        }
        float wA = __expf(lrelu(aA + ald));
        float wB = __expf(lrelu(aB + ald));
        float wC = __expf(lrelu(aC + ald));
        float wD = __expf(lrelu(aD + ald));
        den += (wA + wB) + (wC + wD);
        float2 A0 = h2f(rA.x), A1 = h2f(rA.y);
        float2 B0 = h2f(rB.x), B1 = h2f(rB.y);
        float2 C0 = h2f(rC.x), C1v = h2f(rC.y);
        float2 D0 = h2f(rD.x), D1 = h2f(rD.y);
        acc.x += wA * A0.x + wB * B0.x + wC * C0.x + wD * D0.x;
        acc.y += wA * A0.y + wB * B0.y + wC * C0.y + wD * D0.y;
        acc.z += wA * A1.x + wB * B1.x + wC * C1v.x + wD * D1.x;
        acc.w += wA * A1.y + wB * B1.y + wC * C1v.y + wD * D1.y;
    }
    for (; i < end; i++) {
        int s = __ldg(&g_csr_src[i]);
        float w = __expf(lrelu(__ldg(&g_als2[s]) + ald));
        den += w;
        if (act) {
            uint2 r = *(const uint2*)&g_h2h[s * CLS + lane * 4];
            float2 p0 = h2f(r.x), p1 = h2f(r.y);
            acc.x += w * p0.x; acc.y += w * p0.y;
            acc.z += w * p1.x; acc.w += w * p1.y;
        }
    }
    float inv = 1.f / (den + 1e-16f);
    float4 v = make_float4(-1e30f, -1e30f, -1e30f, -1e30f);
    if (act) {
        float4 bb = *(const float4*)&b2[lane * 4];
        v.x = acc.x * inv + bb.x;
        v.y = acc.y * inv + bb.y;
        v.z = acc.z * inv + bb.z;
        v.w = acc.w * inv + bb.w;
    }
    float m = fmaxf(fmaxf(v.x, v.y), fmaxf(v.z, v.w));
#pragma unroll
    for (int o = 16; o > 0; o >>= 1) m = fmaxf(m, __shfl_xor_sync(0xffffffff, m, o));
    float s4 = 0.f;
    if (act)
        s4 = __expf(v.x - m) + __expf(v.y - m) + __expf(v.z - m) + __expf(v.w - m);
#pragma unroll
    for (int o = 16; o > 0; o >>= 1) s4 += __shfl_xor_sync(0xffffffff, s4, o);
    float lse = m + logf(s4);
    if (act) {
        float4 r;
        r.x = v.x - lse; r.y = v.y - lse; r.z = v.z - lse; r.w = v.w - lse;
        *(float4*)&out[n * CLS + lane * 4] = r;
    }
}

// ---------------- launch ----------------
extern "C" void kernel_launch(void* const* d_in, const int* in_sizes, int n_in,
                              void* d_out, int out_size) {
    const float* x   = (const float*)d_in[0];
    const int*   ei  = (const int*)  d_in[1];
    const float* W1  = (const float*)d_in[2];
    const float* as1 = (const float*)d_in[3];
    const float* ad1 = (const float*)d_in[4];
    const float* b1  = (const float*)d_in[5];
    const float* W2  = (const float*)d_in[6];
    const float* as2 = (const float*)d_in[7];
    const float* ad2 = (const float*)d_in[8];
    const float* b2  = (const float*)d_in[9];
    float* out = (float*)d_out;

    cudaFuncSetAttribute(gemm1_kernel,
                         cudaFuncAttributeMaxDynamicSharedMemorySize, GEMM1_SMEM);

    cudaStream_t s2;
    cudaEvent_t evA, evB;
    cudaStreamCreateWithFlags(&s2, cudaStreamNonBlocking);
    cudaEventCreateWithFlags(&evA, cudaEventDisableTiming);
    cudaEventCreateWithFlags(&evB, cudaEventDisableTiming);

    cudaEventRecord(evA, 0);
    cudaStreamWaitEvent(s2, evA, 0);

    // branch A: CSR build (parallel scan)
    void* cnt_ptr = nullptr;
    cudaGetSymbolAddress(&cnt_ptr, g_cnt);
    cudaMemsetAsync(cnt_ptr, 0, NN * sizeof(int), s2);
    hist_kernel<<<((TOTE + 7) / 8 + 255) / 256, 256, 0, s2>>>(ei);
    scanA_kernel<<<SCANB, 256, 0, s2>>>();
    scanB_kernel<<<1, 256, 0, s2>>>();
    scanC_kernel<<<SCANB, 256, 0, s2>>>();
    scatter_kernel<<<((TOTE + 7) / 8 + 255) / 256, 256, 0, s2>>>(ei);
    cudaEventRecord(evB, s2);

    // branch B: dense layer 1 (tf32 + cp.async) + fused logits
    gemm1_kernel<<<(NN + 127) / 128, 256, GEMM1_SMEM>>>(x, W1, as1, ad1);

    cudaStreamWaitEvent(0, evB, 0);

    agg1_kernel<<<(NN * 32 + 255) / 256, 256>>>(b1);
    l2gemm_kernel<<<(NN + 255) / 256, 256>>>(W2, as2, ad2);
    agg2_kernel<<<(NN * 32 + 255) / 256, 256>>>(b2, out);
}

// round 13
// speedup vs baseline: 1.3166x; 1.3166x over previous
#include <cuda_runtime.h>
#include <cuda_fp16.h>
#include <math.h>

#define NN    50000
#define FIN   128
#define C1    128
#define HEADS 4
#define HID   32
#define CLS   40
#define EE    800000
#define TOTE  (EE + NN)
#define NEG   0.2f
#define SCANB 196            // ceil(NN/256)

// ---------------- scratch ----------------
__device__ __half g_h1h[NN * C1];
__device__ float  g_out1[NN * C1];
__device__ __half g_h2h[NN * CLS];
__device__ float  g_als1[NN * HEADS];
__device__ float  g_ald1[NN * HEADS];
__device__ float  g_als2[NN];
__device__ float  g_ald2[NN];
__device__ int    g_cnt [NN];
__device__ int    g_rowptr[NN + 1];
__device__ int    g_csr_src[TOTE];
__device__ int    g_bsum[256];
__device__ int    g_boff[256];

__device__ __forceinline__ float lrelu(float x) { return x > 0.f ? x : NEG * x; }

__device__ __forceinline__ unsigned long long pk2(float a, float b) {
    unsigned long long r;
    asm("mov.b64 %0, {%1, %2};" : "=l"(r)
        : "r"(__float_as_uint(a)), "r"(__float_as_uint(b)));
    return r;
}
__device__ __forceinline__ void fma2(unsigned long long& d,
                                     unsigned long long a, unsigned long long b) {
    asm("fma.rn.f32x2 %0, %1, %2, %0;" : "+l"(d) : "l"(a), "l"(b));
}
__device__ __forceinline__ float2 up2(unsigned long long p) {
    unsigned int lo, hi;
    asm("mov.b64 {%0, %1}, %2;" : "=r"(lo), "=r"(hi) : "l"(p));
    return make_float2(__uint_as_float(lo), __uint_as_float(hi));
}
__device__ __forceinline__ float2 h2f(unsigned int u) {
    __half2 h = *reinterpret_cast<__half2*>(&u);
    return __half22float2(h);
}
__device__ __forceinline__ unsigned int f2h(float a, float b) {
    __half2 h = __float22half2_rn(make_float2(a, b));
    return *reinterpret_cast<unsigned int*>(&h);
}
__device__ __forceinline__ void mma_tf32(float* c, const unsigned* a, const unsigned* b) {
    asm volatile(
        "mma.sync.aligned.m16n8k8.row.col.f32.tf32.tf32.f32 "
        "{%0,%1,%2,%3}, {%4,%5,%6,%7}, {%8,%9}, {%0,%1,%2,%3};"
        : "+f"(c[0]), "+f"(c[1]), "+f"(c[2]), "+f"(c[3])
        : "r"(a[0]), "r"(a[1]), "r"(a[2]), "r"(a[3]), "r"(b[0]), "r"(b[1]));
}

// ---------------- CSR build ----------------
__global__ void hist_kernel(const int* __restrict__ ei) {
    int q = (blockIdx.x * blockDim.x + threadIdx.x) * 8;
    if (q >= TOTE) return;
    if (q + 8 <= EE) {
        int4 a = *(const int4*)&ei[EE + q];
        int4 b = *(const int4*)&ei[EE + q + 4];
        asm volatile("red.global.add.u32 [%0], %1;" :: "l"(&g_cnt[a.x]), "r"(1) : "memory");
        asm volatile("red.global.add.u32 [%0], %1;" :: "l"(&g_cnt[a.y]), "r"(1) : "memory");
        asm volatile("red.global.add.u32 [%0], %1;" :: "l"(&g_cnt[a.z]), "r"(1) : "memory");
        asm volatile("red.global.add.u32 [%0], %1;" :: "l"(&g_cnt[a.w]), "r"(1) : "memory");
        asm volatile("red.global.add.u32 [%0], %1;" :: "l"(&g_cnt[b.x]), "r"(1) : "memory");
        asm volatile("red.global.add.u32 [%0], %1;" :: "l"(&g_cnt[b.y]), "r"(1) : "memory");
        asm volatile("red.global.add.u32 [%0], %1;" :: "l"(&g_cnt[b.z]), "r"(1) : "memory");
        asm volatile("red.global.add.u32 [%0], %1;" :: "l"(&g_cnt[b.w]), "r"(1) : "memory");
    } else {
        for (int j = 0; j < 8 && q + j < TOTE; j++) {
            int e = q + j;
            int d = (e < EE) ? ei[EE + e] : e - EE;
            asm volatile("red.global.add.u32 [%0], %1;" :: "l"(&g_cnt[d]), "r"(1) : "memory");
        }
    }
}
// blockwise exclusive scan (3 stages)
__global__ void scanA_kernel() {
    __shared__ int sm[256];
    int t = threadIdx.x, i = blockIdx.x * 256 + t;
    int v = (i < NN) ? g_cnt[i] : 0;
    int acc = v;
    sm[t] = acc; __syncthreads();
    for (int off = 1; off < 256; off <<= 1) {
        int u = (t >= off) ? sm[t - off] : 0;
        __syncthreads();
        acc += u; sm[t] = acc;
        __syncthreads();
    }
    if (i < NN) g_rowptr[i] = acc - v;
    if (t == 255) g_bsum[blockIdx.x] = acc;
}
__global__ void scanB_kernel() {
    __shared__ int sm[256];
    int t = threadIdx.x;
    int v = (t < SCANB) ? g_bsum[t] : 0;
    int acc = v;
    sm[t] = acc; __syncthreads();
    for (int off = 1; off < 256; off <<= 1) {
        int u = (t >= off) ? sm[t - off] : 0;
        __syncthreads();
        acc += u; sm[t] = acc;
        __syncthreads();
    }
    g_boff[t] = acc - v;
}
__global__ void scanC_kernel() {
    int t = threadIdx.x, i = blockIdx.x * 256 + t;
    if (i < NN) {
        int r = g_rowptr[i] + g_boff[blockIdx.x];
        g_rowptr[i] = r;
        g_cnt[i] = r;
    }
    if (i == 0) g_rowptr[NN] = TOTE;
}
__global__ void scatter_kernel(const int* __restrict__ ei) {
    int q = (blockIdx.x * blockDim.x + threadIdx.x) * 8;
    if (q >= TOTE) return;
    if (q + 8 <= EE) {
        int4 sa = *(const int4*)&ei[q];
        int4 sb = *(const int4*)&ei[q + 4];
        int4 da = *(const int4*)&ei[EE + q];
        int4 db = *(const int4*)&ei[EE + q + 4];
        int p0 = atomicAdd(&g_cnt[da.x], 1);
        int p1 = atomicAdd(&g_cnt[da.y], 1);
        int p2 = atomicAdd(&g_cnt[da.z], 1);
        int p3 = atomicAdd(&g_cnt[da.w], 1);
        int p4 = atomicAdd(&g_cnt[db.x], 1);
        int p5 = atomicAdd(&g_cnt[db.y], 1);
        int p6 = atomicAdd(&g_cnt[db.z], 1);
        int p7 = atomicAdd(&g_cnt[db.w], 1);
        g_csr_src[p0] = sa.x; g_csr_src[p1] = sa.y;
        g_csr_src[p2] = sa.z; g_csr_src[p3] = sa.w;
        g_csr_src[p4] = sb.x; g_csr_src[p5] = sb.y;
        g_csr_src[p6] = sb.z; g_csr_src[p7] = sb.w;
    } else {
        for (int j = 0; j < 8 && q + j < TOTE; j++) {
            int e = q + j;
            int s, d;
            if (e < EE) { s = ei[e]; d = ei[EE + e]; } else { s = d = e - EE; }
            int pos = atomicAdd(&g_cnt[d], 1);
            g_csr_src[pos] = s;
        }
    }
}

// ---------------- GEMM1 (tf32 tensor core, R8 sync structure) + fused logits ----------------
__global__ __launch_bounds__(256, 2) void gemm1_kernel(const float* __restrict__ x,
                                                       const float* __restrict__ W,
                                                       const float* __restrict__ att_s,
                                                       const float* __restrict__ att_d) {
    __shared__ __align__(16) float xs[128][36];    // [row][k], pad 4
    __shared__ __align__(16) float ws[32][136];    // [k][col], pad 8
    __shared__ __align__(16) float ps_s[128][4];
    __shared__ __align__(16) float pd_s[128][4];

    int t = threadIdx.x;
    int row0 = blockIdx.x * 128;
    int w = t >> 5, lane = t & 31;
    int wm = w & 3, wn = w >> 2;
    int q = lane >> 2, rsub = lane & 3;

    if (t < 128) *(float4*)&ps_s[t][0] = make_float4(0.f, 0.f, 0.f, 0.f);
    else         *(float4*)&pd_s[t - 128][0] = make_float4(0.f, 0.f, 0.f, 0.f);

    float c[2][8][4];
#pragma unroll
    for (int mt = 0; mt < 2; mt++)
#pragma unroll
        for (int nt = 0; nt < 8; nt++)
#pragma unroll
            for (int i = 0; i < 4; i++) c[mt][nt][i] = 0.f;

    for (int k0 = 0; k0 < FIN; k0 += 32) {
#pragma unroll
        for (int j = 0; j < 4; j++) {
            int idx = t + 256 * j;
            int r = idx >> 3, kq = idx & 7;
            int gr = row0 + r;
            float4 v = make_float4(0.f, 0.f, 0.f, 0.f);
            if (gr < NN) v = *(const float4*)&x[gr * FIN + k0 + kq * 4];
            *(float4*)&xs[r][kq * 4] = v;      // raw fp32; mma truncates to tf32
        }
#pragma unroll
        for (int j = 0; j < 4; j++) {
            int idx = t + 256 * j;
            int kk = idx >> 5, c4 = idx & 31;
            *(float4*)&ws[kk][c4 * 4] = *(const float4*)&W[(k0 + kk) * C1 + c4 * 4];
        }
        __syncthreads();
#pragma unroll
        for (int ks = 0; ks < 4; ks++) {
            int kb = ks * 8;
            unsigned af[2][4];
#pragma unroll
            for (int mt = 0; mt < 2; mt++) {
                int rb = wm * 32 + mt * 16;
                af[mt][0] = __float_as_uint(xs[rb + q    ][kb + rsub    ]);
                af[mt][1] = __float_as_uint(xs[rb + q + 8][kb + rsub    ]);
                af[mt][2] = __float_as_uint(xs[rb + q    ][kb + rsub + 4]);
                af[mt][3] = __float_as_uint(xs[rb + q + 8][kb + rsub + 4]);
            }
            unsigned bf[8][2];
#pragma unroll
            for (int nt = 0; nt < 8; nt++) {
                int col = wn * 64 + nt * 8 + q;
                bf[nt][0] = __float_as_uint(ws[kb + rsub    ][col]);
                bf[nt][1] = __float_as_uint(ws[kb + rsub + 4][col]);
            }
#pragma unroll
            for (int mt = 0; mt < 2; mt++)
#pragma unroll
                for (int nt = 0; nt < 8; nt++)
                    mma_tf32(c[mt][nt], af[mt], bf[nt]);
        }
        __syncthreads();
    }

    // ---- epilogue: store h1 (fp16) + per-head logit partials ----
    float2 asv[8], adv[8];
#pragma unroll
    for (int nt = 0; nt < 8; nt++) {
        int col = wn * 64 + nt * 8 + 2 * rsub;
        asv[nt] = *(const float2*)&att_s[col];
        adv[nt] = *(const float2*)&att_d[col];
    }
#pragma unroll
    for (int mt = 0; mt < 2; mt++) {
        int rloc0 = wm * 32 + mt * 16 + q;
        int rloc1 = rloc0 + 8;
        float psl0 = 0.f, psh0 = 0.f, pdl0 = 0.f, pdh0 = 0.f;
        float psl1 = 0.f, psh1 = 0.f, pdl1 = 0.f, pdh1 = 0.f;
#pragma unroll
        for (int nt = 0; nt < 8; nt++) {
            float c0 = c[mt][nt][0], c1 = c[mt][nt][1];
            float c2 = c[mt][nt][2], c3 = c[mt][nt][3];
            float s0 = c0 * asv[nt].x + c1 * asv[nt].y;
            float d0 = c0 * adv[nt].x + c1 * adv[nt].y;
            float s1 = c2 * asv[nt].x + c3 * asv[nt].y;
            float d1 = c2 * adv[nt].x + c3 * adv[nt].y;
            if (nt < 4) { psl0 += s0; pdl0 += d0; psl1 += s1; pdl1 += d1; }
            else        { psh0 += s0; pdh0 += d0; psh1 += s1; pdh1 += d1; }
            int colg = wn * 64 + nt * 8 + 2 * rsub;
            int gr0 = row0 + rloc0, gr1 = row0 + rloc1;
            if (gr0 < NN) *(unsigned*)&g_h1h[gr0 * C1 + colg] = f2h(c0, c1);
            if (gr1 < NN) *(unsigned*)&g_h1h[gr1 * C1 + colg] = f2h(c2, c3);
        }
#pragma unroll
        for (int o = 1; o < 4; o <<= 1) {
            psl0 += __shfl_down_sync(0xffffffff, psl0, o, 4);
            psh0 += __shfl_down_sync(0xffffffff, psh0, o, 4);
            pdl0 += __shfl_down_sync(0xffffffff, pdl0, o, 4);
            pdh0 += __shfl_down_sync(0xffffffff, pdh0, o, 4);
            psl1 += __shfl_down_sync(0xffffffff, psl1, o, 4);
            psh1 += __shfl_down_sync(0xffffffff, psh1, o, 4);
            pdl1 += __shfl_down_sync(0xffffffff, pdl1, o, 4);
            pdh1 += __shfl_down_sync(0xffffffff, pdh1, o, 4);
        }
        if (rsub == 0) {
            int hlo = wn * 2, hhi = wn * 2 + 1;
            atomicAdd(&ps_s[rloc0][hlo], psl0);
            atomicAdd(&ps_s[rloc0][hhi], psh0);
            atomicAdd(&pd_s[rloc0][hlo], pdl0);
            atomicAdd(&pd_s[rloc0][hhi], pdh0);
            atomicAdd(&ps_s[rloc1][hlo], psl1);
            atomicAdd(&ps_s[rloc1][hhi], psh1);
            atomicAdd(&pd_s[rloc1][hlo], pdl1);
            atomicAdd(&pd_s[rloc1][hhi], pdh1);
        }
    }
    __syncthreads();
    if (t < 128) {
        int gr = row0 + t;
        if (gr < NN) *(float4*)&g_als1[gr * HEADS] = *(float4*)&ps_s[t][0];
    } else {
        int rr = t - 128;
        int gr = row0 + rr;
        if (gr < NN) *(float4*)&g_ald1[gr * HEADS] = *(float4*)&pd_s[rr][0];
    }
}

// ---------------- layer-1 aggregation: 2 warps per node (64 feats each) ----------------
__global__ void agg1_kernel(const float* __restrict__ b1) {
    int gt = blockIdx.x * blockDim.x + threadIdx.x;
    int n = gt >> 6;                       // 64 threads per node
    if (n >= NN) return;
    int lane = gt & 31;
    int sub = (gt >> 5) & 1;
    int fo = sub * 64 + lane * 2;          // feature (half) offset: this lane owns 2
    int h = fo >> 5;                       // head of these 2 features
    float ald = g_ald1[n * HEADS + h];
    int beg = g_rowptr[n], end = g_rowptr[n + 1];
    float2 acc = make_float2(0.f, 0.f);
    float den = 0.f;
    int i = beg;
    for (; i + 4 <= end; i += 4) {
        int sA = __ldg(&g_csr_src[i]);
        int sB = __ldg(&g_csr_src[i + 1]);
        int sC = __ldg(&g_csr_src[i + 2]);
        int sD = __ldg(&g_csr_src[i + 3]);
        float aA = __ldg(&g_als1[sA * HEADS + h]);
        float aB = __ldg(&g_als1[sB * HEADS + h]);
        float aC = __ldg(&g_als1[sC * HEADS + h]);
        float aD = __ldg(&g_als1[sD * HEADS + h]);
        unsigned rA = *(const unsigned*)&g_h1h[sA * C1 + fo];
        unsigned rB = *(const unsigned*)&g_h1h[sB * C1 + fo];
        unsigned rC = *(const unsigned*)&g_h1h[sC * C1 + fo];
        unsigned rD = *(const unsigned*)&g_h1h[sD * C1 + fo];
        float wA = __expf(lrelu(aA + ald));
        float wB = __expf(lrelu(aB + ald));
        float wC = __expf(lrelu(aC + ald));
        float wD = __expf(lrelu(aD + ald));
        den += (wA + wB) + (wC + wD);
        float2 A = h2f(rA), B = h2f(rB), C = h2f(rC), D = h2f(rD);
        acc.x += wA * A.x + wB * B.x + wC * C.x + wD * D.x;
        acc.y += wA * A.y + wB * B.y + wC * C.y + wD * D.y;
    }
    for (; i < end; i++) {
        int s = __ldg(&g_csr_src[i]);
        float wv = __expf(lrelu(__ldg(&g_als1[s * HEADS + h]) + ald));
        den += wv;
        float2 p = h2f(*(const unsigned*)&g_h1h[s * C1 + fo]);
        acc.x += wv * p.x;
        acc.y += wv * p.y;
    }
    float inv = 1.f / (den + 1e-16f);
    float2 bb = *(const float2*)&b1[fo];
    float2 o;
    o.x = fmaxf(acc.x * inv + bb.x, 0.f);
    o.y = fmaxf(acc.y * inv + bb.y, 0.f);
    *(float2*)&g_out1[n * C1 + fo] = o;
}

// ---------------- GEMM2 + layer-2 logits ----------------
__global__ __launch_bounds__(256) void l2gemm_kernel(const float* __restrict__ W2,
                                                     const float* __restrict__ as2,
                                                     const float* __restrict__ ad2) {
    __shared__ __align__(16) float W2s[FIN * CLS];
    __shared__ float s2s[CLS], d2s[CLS];
    int t = threadIdx.x;
    for (int i = t; i < FIN * CLS; i += 256) W2s[i] = W2[i];
    if (t < CLS) { s2s[t] = as2[t]; d2s[t] = ad2[t]; }
    __syncthreads();

    int n = blockIdx.x * blockDim.x + t;
    if (n >= NN) return;
    unsigned long long acc[20];
#pragma unroll
    for (int c = 0; c < 20; c++) acc[c] = 0ULL;

    for (int k = 0; k < FIN; k += 4) {
        float4 r4 = *(const float4*)&g_out1[n * FIN + k];
        float rv[4] = {r4.x, r4.y, r4.z, r4.w};
#pragma unroll
        for (int qq = 0; qq < 4; qq++) {
            unsigned long long rp = pk2(rv[qq], rv[qq]);
            const float* wrow = &W2s[(k + qq) * CLS];
#pragma unroll
            for (int c4 = 0; c4 < 10; c4++) {
                ulonglong2 wp = *(const ulonglong2*)&wrow[c4 * 4];
                fma2(acc[c4 * 2 + 0], rp, wp.x);
                fma2(acc[c4 * 2 + 1], rp, wp.y);
            }
        }
    }
    float ls = 0.f, ld = 0.f;
    unsigned int hp[20];
#pragma unroll
    for (int c2 = 0; c2 < 20; c2++) {
        float2 v = up2(acc[c2]);
        hp[c2] = f2h(v.x, v.y);
        ls += v.x * s2s[c2 * 2] + v.y * s2s[c2 * 2 + 1];
        ld += v.x * d2s[c2 * 2] + v.y * d2s[c2 * 2 + 1];
    }
    uint4* dst = (uint4*)&g_h2h[n * CLS];
#pragma unroll
    for (int j = 0; j < 5; j++) {
        uint4 u;
        u.x = hp[j * 4 + 0]; u.y = hp[j * 4 + 1];
        u.z = hp[j * 4 + 2]; u.w = hp[j * 4 + 3];
        dst[j] = u;
    }
    g_als2[n] = ls;
    g_ald2[n] = ld;
}

// ---------------- layer-2 aggregation + bias + log_softmax ----------------
__global__ void agg2_kernel(const float* __restrict__ b2, float* __restrict__ out) {
    int gt = blockIdx.x * blockDim.x + threadIdx.x;
    int n = gt >> 5, lane = gt & 31;
    if (n >= NN) return;
    float ald = g_ald2[n];
    int beg = g_rowptr[n], end = g_rowptr[n + 1];
    bool act = lane < 10;
    float4 acc = make_float4(0.f, 0.f, 0.f, 0.f);
    float den = 0.f;
    int i = beg;
    for (; i + 4 <= end; i += 4) {
        int sA = __ldg(&g_csr_src[i]);
        int sB = __ldg(&g_csr_src[i + 1]);
        int sC = __ldg(&g_csr_src[i + 2]);
        int sD = __ldg(&g_csr_src[i + 3]);
        float aA = __ldg(&g_als2[sA]);
        float aB = __ldg(&g_als2[sB]);
        float aC = __ldg(&g_als2[sC]);
        float aD = __ldg(&g_als2[sD]);
        uint2 rA = make_uint2(0u, 0u), rB = rA, rC = rA, rD = rA;
        if (act) {
            rA = *(const uint2*)&g_h2h[sA * CLS + lane * 4];
            rB = *(const uint2*)&g_h2h[sB * CLS + lane * 4];
            rC = *(const uint2*)&g_h2h[sC * CLS + lane * 4];
            rD = *(const uint2*)&g_h2h[sD * CLS + lane * 4];
        }
        float wA = __expf(lrelu(aA + ald));
        float wB = __expf(lrelu(aB + ald));
        float wC = __expf(lrelu(aC + ald));
        float wD = __expf(lrelu(aD + ald));
        den += (wA + wB) + (wC + wD);
        float2 A0 = h2f(rA.x), A1 = h2f(rA.y);
        float2 B0 = h2f(rB.x), B1 = h2f(rB.y);
        float2 C0 = h2f(rC.x), C1v = h2f(rC.y);
        float2 D0 = h2f(rD.x), D1 = h2f(rD.y);
        acc.x += wA * A0.x + wB * B0.x + wC * C0.x + wD * D0.x;
        acc.y += wA * A0.y + wB * B0.y + wC * C0.y + wD * D0.y;
        acc.z += wA * A1.x + wB * B1.x + wC * C1v.x + wD * D1.x;
        acc.w += wA * A1.y + wB * B1.y + wC * C1v.y + wD * D1.y;
    }
    for (; i < end; i++) {
        int s = __ldg(&g_csr_src[i]);
        float wv = __expf(lrelu(__ldg(&g_als2[s]) + ald));
        den += wv;
        if (act) {
            uint2 r = *(const uint2*)&g_h2h[s * CLS + lane * 4];
            float2 p0 = h2f(r.x), p1 = h2f(r.y);
            acc.x += wv * p0.x; acc.y += wv * p0.y;
            acc.z += wv * p1.x; acc.w += wv * p1.y;
        }
    }
    float inv = 1.f / (den + 1e-16f);
    float4 v = make_float4(-1e30f, -1e30f, -1e30f, -1e30f);
    if (act) {
        float4 bb = *(const float4*)&b2[lane * 4];
        v.x = acc.x * inv + bb.x;
        v.y = acc.y * inv + bb.y;
        v.z = acc.z * inv + bb.z;
        v.w = acc.w * inv + bb.w;
    }
    float m = fmaxf(fmaxf(v.x, v.y), fmaxf(v.z, v.w));
#pragma unroll
    for (int o = 16; o > 0; o >>= 1) m = fmaxf(m, __shfl_xor_sync(0xffffffff, m, o));
    float s4 = 0.f;
    if (act)
        s4 = __expf(v.x - m) + __expf(v.y - m) + __expf(v.z - m) + __expf(v.w - m);
#pragma unroll
    for (int o = 16; o > 0; o >>= 1) s4 += __shfl_xor_sync(0xffffffff, s4, o);
    float lse = m + logf(s4);
    if (act) {
        float4 r;
        r.x = v.x - lse; r.y = v.y - lse; r.z = v.z - lse; r.w = v.w - lse;
        *(float4*)&out[n * CLS + lane * 4] = r;
    }
}

// ---------------- launch ----------------
extern "C" void kernel_launch(void* const* d_in, const int* in_sizes, int n_in,
                              void* d_out, int out_size) {
    const float* x   = (const float*)d_in[0];
    const int*   ei  = (const int*)  d_in[1];
    const float* W1  = (const float*)d_in[2];
    const float* as1 = (const float*)d_in[3];
    const float* ad1 = (const float*)d_in[4];
    const float* b1  = (const float*)d_in[5];
    const float* W2  = (const float*)d_in[6];
    const float* as2 = (const float*)d_in[7];
    const float* ad2 = (const float*)d_in[8];
    const float* b2  = (const float*)d_in[9];
    float* out = (float*)d_out;

    cudaStream_t s2;
    cudaEvent_t evA, evB;
    cudaStreamCreateWithFlags(&s2, cudaStreamNonBlocking);
    cudaEventCreateWithFlags(&evA, cudaEventDisableTiming);
    cudaEventCreateWithFlags(&evB, cudaEventDisableTiming);

    cudaEventRecord(evA, 0);
    cudaStreamWaitEvent(s2, evA, 0);

    // branch A: CSR build (parallel scan)
    void* cnt_ptr = nullptr;
    cudaGetSymbolAddress(&cnt_ptr, g_cnt);
    cudaMemsetAsync(cnt_ptr, 0, NN * sizeof(int), s2);
    hist_kernel<<<((TOTE + 7) / 8 + 255) / 256, 256, 0, s2>>>(ei);
    scanA_kernel<<<SCANB, 256, 0, s2>>>();
    scanB_kernel<<<1, 256, 0, s2>>>();
    scanC_kernel<<<SCANB, 256, 0, s2>>>();
    scatter_kernel<<<((TOTE + 7) / 8 + 255) / 256, 256, 0, s2>>>(ei);
    cudaEventRecord(evB, s2);

    // branch B: dense layer 1 (tf32 sync, R8 structure) + fused logits
    gemm1_kernel<<<(NN + 127) / 128, 256>>>(x, W1, as1, ad1);

    cudaStreamWaitEvent(0, evB, 0);

    agg1_kernel<<<(NN * 64 + 255) / 256, 256>>>(b1);
    l2gemm_kernel<<<(NN + 255) / 256, 256>>>(W2, as2, ad2);
    agg2_kernel<<<(NN * 32 + 255) / 256, 256>>>(b2, out);
}

// round 16
// speedup vs baseline: 1.4032x; 1.0658x over previous
#include <cuda_runtime.h>
#include <cuda_fp16.h>
#include <math.h>

#define NN    50000
#define FIN   128
#define C1    128
#define HEADS 4
#define HID   32
#define CLS   40
#define EE    800000
#define TOTE  (EE + NN)
#define NEG   0.2f
#define SCANB 196            // ceil(NN/256)

// ---------------- scratch ----------------
__device__ __half g_h1h[NN * C1];
__device__ float  g_out1[NN * C1];
__device__ __half g_h2h[NN * CLS];
__device__ float  g_als1[NN * HEADS];
__device__ float  g_ald1[NN * HEADS];
__device__ float  g_als2[NN];
__device__ float  g_ald2[NN];
__device__ int    g_cnt [NN];
__device__ int    g_rowptr[NN + 1];
__device__ int    g_csr_src[TOTE];
__device__ int    g_bsum[256];
__device__ int    g_boff[256];

__device__ __forceinline__ float lrelu(float x) { return x > 0.f ? x : NEG * x; }

__device__ __forceinline__ unsigned long long pk2(float a, float b) {
    unsigned long long r;
    asm("mov.b64 %0, {%1, %2};" : "=l"(r)
        : "r"(__float_as_uint(a)), "r"(__float_as_uint(b)));
    return r;
}
__device__ __forceinline__ void fma2(unsigned long long& d,
                                     unsigned long long a, unsigned long long b) {
    asm("fma.rn.f32x2 %0, %1, %2, %0;" : "+l"(d) : "l"(a), "l"(b));
}
__device__ __forceinline__ float2 up2(unsigned long long p) {
    unsigned int lo, hi;
    asm("mov.b64 {%0, %1}, %2;" : "=r"(lo), "=r"(hi) : "l"(p));
    return make_float2(__uint_as_float(lo), __uint_as_float(hi));
}
__device__ __forceinline__ float2 h2f(unsigned int u) {
    __half2 h = *reinterpret_cast<__half2*>(&u);
    return __half22float2(h);
}
__device__ __forceinline__ unsigned int f2h(float a, float b) {
    __half2 h = __float22half2_rn(make_float2(a, b));
    return *reinterpret_cast<unsigned int*>(&h);
}
__device__ __forceinline__ void mma_tf32(float* c, const unsigned* a, const unsigned* b) {
    asm volatile(
        "mma.sync.aligned.m16n8k8.row.col.f32.tf32.tf32.f32 "
        "{%0,%1,%2,%3}, {%4,%5,%6,%7}, {%8,%9}, {%0,%1,%2,%3};"
        : "+f"(c[0]), "+f"(c[1]), "+f"(c[2]), "+f"(c[3])
        : "r"(a[0]), "r"(a[1]), "r"(a[2]), "r"(a[3]), "r"(b[0]), "r"(b[1]));
}

// ---------------- CSR build ----------------
__global__ void hist_kernel(const int* __restrict__ ei) {
    int q = (blockIdx.x * blockDim.x + threadIdx.x) * 8;
    if (q >= TOTE) return;
    if (q + 8 <= EE) {
        int4 a = *(const int4*)&ei[EE + q];
        int4 b = *(const int4*)&ei[EE + q + 4];
        asm volatile("red.global.add.u32 [%0], %1;" :: "l"(&g_cnt[a.x]), "r"(1) : "memory");
        asm volatile("red.global.add.u32 [%0], %1;" :: "l"(&g_cnt[a.y]), "r"(1) : "memory");
        asm volatile("red.global.add.u32 [%0], %1;" :: "l"(&g_cnt[a.z]), "r"(1) : "memory");
        asm volatile("red.global.add.u32 [%0], %1;" :: "l"(&g_cnt[a.w]), "r"(1) : "memory");
        asm volatile("red.global.add.u32 [%0], %1;" :: "l"(&g_cnt[b.x]), "r"(1) : "memory");
        asm volatile("red.global.add.u32 [%0], %1;" :: "l"(&g_cnt[b.y]), "r"(1) : "memory");
        asm volatile("red.global.add.u32 [%0], %1;" :: "l"(&g_cnt[b.z]), "r"(1) : "memory");
        asm volatile("red.global.add.u32 [%0], %1;" :: "l"(&g_cnt[b.w]), "r"(1) : "memory");
    } else {
        for (int j = 0; j < 8 && q + j < TOTE; j++) {
            int e = q + j;
            int d = (e < EE) ? ei[EE + e] : e - EE;
            asm volatile("red.global.add.u32 [%0], %1;" :: "l"(&g_cnt[d]), "r"(1) : "memory");
        }
    }
}
// blockwise exclusive scan (3 stages)
__global__ void scanA_kernel() {
    __shared__ int sm[256];
    int t = threadIdx.x, i = blockIdx.x * 256 + t;
    int v = (i < NN) ? g_cnt[i] : 0;
    int acc = v;
    sm[t] = acc; __syncthreads();
    for (int off = 1; off < 256; off <<= 1) {
        int u = (t >= off) ? sm[t - off] : 0;
        __syncthreads();
        acc += u; sm[t] = acc;
        __syncthreads();
    }
    if (i < NN) g_rowptr[i] = acc - v;
    if (t == 255) g_bsum[blockIdx.x] = acc;
}
__global__ void scanB_kernel() {
    __shared__ int sm[256];
    int t = threadIdx.x;
    int v = (t < SCANB) ? g_bsum[t] : 0;
    int acc = v;
    sm[t] = acc; __syncthreads();
    for (int off = 1; off < 256; off <<= 1) {
        int u = (t >= off) ? sm[t - off] : 0;
        __syncthreads();
        acc += u; sm[t] = acc;
        __syncthreads();
    }
    g_boff[t] = acc - v;
}
__global__ void scanC_kernel() {
    int t = threadIdx.x, i = blockIdx.x * 256 + t;
    if (i < NN) {
        int r = g_rowptr[i] + g_boff[blockIdx.x];
        g_rowptr[i] = r;
        g_cnt[i] = r;
    }
    if (i == 0) g_rowptr[NN] = TOTE;
}
__global__ void scatter_kernel(const int* __restrict__ ei) {
    int q = (blockIdx.x * blockDim.x + threadIdx.x) * 8;
    if (q >= TOTE) return;
    if (q + 8 <= EE) {
        int4 sa = *(const int4*)&ei[q];
        int4 sb = *(const int4*)&ei[q + 4];
        int4 da = *(const int4*)&ei[EE + q];
        int4 db = *(const int4*)&ei[EE + q + 4];
        int p0 = atomicAdd(&g_cnt[da.x], 1);
        int p1 = atomicAdd(&g_cnt[da.y], 1);
        int p2 = atomicAdd(&g_cnt[da.z], 1);
        int p3 = atomicAdd(&g_cnt[da.w], 1);
        int p4 = atomicAdd(&g_cnt[db.x], 1);
        int p5 = atomicAdd(&g_cnt[db.y], 1);
        int p6 = atomicAdd(&g_cnt[db.z], 1);
        int p7 = atomicAdd(&g_cnt[db.w], 1);
        g_csr_src[p0] = sa.x; g_csr_src[p1] = sa.y;
        g_csr_src[p2] = sa.z; g_csr_src[p3] = sa.w;
        g_csr_src[p4] = sb.x; g_csr_src[p5] = sb.y;
        g_csr_src[p6] = sb.z; g_csr_src[p7] = sb.w;
    } else {
        for (int j = 0; j < 8 && q + j < TOTE; j++) {
            int e = q + j;
            int s, d;
            if (e < EE) { s = ei[e]; d = ei[EE + e]; } else { s = d = e - EE; }
            int pos = atomicAdd(&g_cnt[d], 1);
            g_csr_src[pos] = s;
        }
    }
}

// ---------------- GEMM1 (tf32 tensor core, R8 sync structure) + fused logits ----------------
__global__ __launch_bounds__(256, 2) void gemm1_kernel(const float* __restrict__ x,
                                                       const float* __restrict__ W,
                                                       const float* __restrict__ att_s,
                                                       const float* __restrict__ att_d) {
    __shared__ __align__(16) float xs[128][36];    // [row][k], pad 4
    __shared__ __align__(16) float ws[32][136];    // [k][col], pad 8
    __shared__ __align__(16) float ps_s[128][4];
    __shared__ __align__(16) float pd_s[128][4];

    int t = threadIdx.x;
    int row0 = blockIdx.x * 128;
    int w = t >> 5, lane = t & 31;
    int wm = w & 3, wn = w >> 2;
    int q = lane >> 2, rsub = lane & 3;

    if (t < 128) *(float4*)&ps_s[t][0] = make_float4(0.f, 0.f, 0.f, 0.f);
    else         *(float4*)&pd_s[t - 128][0] = make_float4(0.f, 0.f, 0.f, 0.f);

    float c[2][8][4];
#pragma unroll
    for (int mt = 0; mt < 2; mt++)
#pragma unroll
        for (int nt = 0; nt < 8; nt++)
#pragma unroll
            for (int i = 0; i < 4; i++) c[mt][nt][i] = 0.f;

    for (int k0 = 0; k0 < FIN; k0 += 32) {
#pragma unroll
        for (int j = 0; j < 4; j++) {
            int idx = t + 256 * j;
            int r = idx >> 3, kq = idx & 7;
            int gr = row0 + r;
            float4 v = make_float4(0.f, 0.f, 0.f, 0.f);
            if (gr < NN) v = *(const float4*)&x[gr * FIN + k0 + kq * 4];
            *(float4*)&xs[r][kq * 4] = v;      // raw fp32; mma truncates to tf32
        }
#pragma unroll
        for (int j = 0; j < 4; j++) {
            int idx = t + 256 * j;
            int kk = idx >> 5, c4 = idx & 31;
            *(float4*)&ws[kk][c4 * 4] = *(const float4*)&W[(k0 + kk) * C1 + c4 * 4];
        }
        __syncthreads();
#pragma unroll
        for (int ks = 0; ks < 4; ks++) {
            int kb = ks * 8;
            unsigned af[2][4];
#pragma unroll
            for (int mt = 0; mt < 2; mt++) {
                int rb = wm * 32 + mt * 16;
                af[mt][0] = __float_as_uint(xs[rb + q    ][kb + rsub    ]);
                af[mt][1] = __float_as_uint(xs[rb + q + 8][kb + rsub    ]);
                af[mt][2] = __float_as_uint(xs[rb + q    ][kb + rsub + 4]);
                af[mt][3] = __float_as_uint(xs[rb + q + 8][kb + rsub + 4]);
            }
            unsigned bf[8][2];
#pragma unroll
            for (int nt = 0; nt < 8; nt++) {
                int col = wn * 64 + nt * 8 + q;
                bf[nt][0] = __float_as_uint(ws[kb + rsub    ][col]);
                bf[nt][1] = __float_as_uint(ws[kb + rsub + 4][col]);
            }
#pragma unroll
            for (int mt = 0; mt < 2; mt++)
#pragma unroll
                for (int nt = 0; nt < 8; nt++)
                    mma_tf32(c[mt][nt], af[mt], bf[nt]);
        }
        __syncthreads();
    }

    // ---- epilogue: store h1 (fp16) + per-head logit partials ----
    float2 asv[8], adv[8];
#pragma unroll
    for (int nt = 0; nt < 8; nt++) {
        int col = wn * 64 + nt * 8 + 2 * rsub;
        asv[nt] = *(const float2*)&att_s[col];
        adv[nt] = *(const float2*)&att_d[col];
    }
#pragma unroll
    for (int mt = 0; mt < 2; mt++) {
        int rloc0 = wm * 32 + mt * 16 + q;
        int rloc1 = rloc0 + 8;
        float psl0 = 0.f, psh0 = 0.f, pdl0 = 0.f, pdh0 = 0.f;
        float psl1 = 0.f, psh1 = 0.f, pdl1 = 0.f, pdh1 = 0.f;
#pragma unroll
        for (int nt = 0; nt < 8; nt++) {
            float c0 = c[mt][nt][0], c1 = c[mt][nt][1];
            float c2 = c[mt][nt][2], c3 = c[mt][nt][3];
            float s0 = c0 * asv[nt].x + c1 * asv[nt].y;
            float d0 = c0 * adv[nt].x + c1 * adv[nt].y;
            float s1 = c2 * asv[nt].x + c3 * asv[nt].y;
            float d1 = c2 * adv[nt].x + c3 * adv[nt].y;
            if (nt < 4) { psl0 += s0; pdl0 += d0; psl1 += s1; pdl1 += d1; }
            else        { psh0 += s0; pdh0 += d0; psh1 += s1; pdh1 += d1; }
            int colg = wn * 64 + nt * 8 + 2 * rsub;
            int gr0 = row0 + rloc0, gr1 = row0 + rloc1;
            if (gr0 < NN) *(unsigned*)&g_h1h[gr0 * C1 + colg] = f2h(c0, c1);
            if (gr1 < NN) *(unsigned*)&g_h1h[gr1 * C1 + colg] = f2h(c2, c3);
        }
#pragma unroll
        for (int o = 1; o < 4; o <<= 1) {
            psl0 += __shfl_down_sync(0xffffffff, psl0, o, 4);
            psh0 += __shfl_down_sync(0xffffffff, psh0, o, 4);
            pdl0 += __shfl_down_sync(0xffffffff, pdl0, o, 4);
            pdh0 += __shfl_down_sync(0xffffffff, pdh0, o, 4);
            psl1 += __shfl_down_sync(0xffffffff, psl1, o, 4);
            psh1 += __shfl_down_sync(0xffffffff, psh1, o, 4);
            pdl1 += __shfl_down_sync(0xffffffff, pdl1, o, 4);
            pdh1 += __shfl_down_sync(0xffffffff, pdh1, o, 4);
        }
        if (rsub == 0) {
            int hlo = wn * 2, hhi = wn * 2 + 1;
            atomicAdd(&ps_s[rloc0][hlo], psl0);
            atomicAdd(&ps_s[rloc0][hhi], psh0);
            atomicAdd(&pd_s[rloc0][hlo], pdl0);
            atomicAdd(&pd_s[rloc0][hhi], pdh0);
            atomicAdd(&ps_s[rloc1][hlo], psl1);
            atomicAdd(&ps_s[rloc1][hhi], psh1);
            atomicAdd(&pd_s[rloc1][hlo], pdl1);
            atomicAdd(&pd_s[rloc1][hhi], pdh1);
        }
    }
    __syncthreads();
    if (t < 128) {
        int gr = row0 + t;
        if (gr < NN) *(float4*)&g_als1[gr * HEADS] = *(float4*)&ps_s[t][0];
    } else {
        int rr = t - 128;
        int gr = row0 + rr;
        if (gr < NN) *(float4*)&g_ald1[gr * HEADS] = *(float4*)&pd_s[rr][0];
    }
}

// ---------------- layer-1 aggregation: 2 warps/node, 8-edge batches ----------------
__global__ void agg1_kernel(const float* __restrict__ b1) {
    int gt = blockIdx.x * blockDim.x + threadIdx.x;
    int n = gt >> 6;                       // 64 threads per node
    if (n >= NN) return;
    int lane = gt & 31;
    int sub = (gt >> 5) & 1;
    int fo = sub * 64 + lane * 2;          // this lane owns 2 features
    int h = fo >> 5;
    float ald = g_ald1[n * HEADS + h];
    int beg = g_rowptr[n], end = g_rowptr[n + 1];
    float2 acc = make_float2(0.f, 0.f);
    float den = 0.f;
    int i = beg;
    for (; i + 8 <= end; i += 8) {
        int s[8]; float a[8]; unsigned r[8]; float wv[8];
#pragma unroll
        for (int j = 0; j < 8; j++) s[j] = __ldg(&g_csr_src[i + j]);
#pragma unroll
        for (int j = 0; j < 8; j++) a[j] = __ldg(&g_als1[s[j] * HEADS + h]);
#pragma unroll
        for (int j = 0; j < 8; j++) r[j] = *(const unsigned*)&g_h1h[s[j] * C1 + fo];
#pragma unroll
        for (int j = 0; j < 8; j++) { wv[j] = __expf(lrelu(a[j] + ald)); den += wv[j]; }
#pragma unroll
        for (int j = 0; j < 8; j++) {
            float2 p = h2f(r[j]);
            acc.x += wv[j] * p.x;
            acc.y += wv[j] * p.y;
        }
    }
    if (i + 4 <= end) {
        int s[4]; float a[4]; unsigned r[4]; float wv[4];
#pragma unroll
        for (int j = 0; j < 4; j++) s[j] = __ldg(&g_csr_src[i + j]);
#pragma unroll
        for (int j = 0; j < 4; j++) a[j] = __ldg(&g_als1[s[j] * HEADS + h]);
#pragma unroll
        for (int j = 0; j < 4; j++) r[j] = *(const unsigned*)&g_h1h[s[j] * C1 + fo];
#pragma unroll
        for (int j = 0; j < 4; j++) { wv[j] = __expf(lrelu(a[j] + ald)); den += wv[j]; }
#pragma unroll
        for (int j = 0; j < 4; j++) {
            float2 p = h2f(r[j]);
            acc.x += wv[j] * p.x;
            acc.y += wv[j] * p.y;
        }
        i += 4;
    }
    for (; i < end; i++) {
        int s = __ldg(&g_csr_src[i]);
        float wv = __expf(lrelu(__ldg(&g_als1[s * HEADS + h]) + ald));
        den += wv;
        float2 p = h2f(*(const unsigned*)&g_h1h[s * C1 + fo]);
        acc.x += wv * p.x;
        acc.y += wv * p.y;
    }
    float inv = 1.f / (den + 1e-16f);
    float2 bb = *(const float2*)&b1[fo];
    float2 o;
    o.x = fmaxf(acc.x * inv + bb.x, 0.f);
    o.y = fmaxf(acc.y * inv + bb.y, 0.f);
    *(float2*)&g_out1[n * C1 + fo] = o;
}

// ---------------- GEMM2 + layer-2 logits ----------------
__global__ __launch_bounds__(256) void l2gemm_kernel(const float* __restrict__ W2,
                                                     const float* __restrict__ as2,
                                                     const float* __restrict__ ad2) {
    __shared__ __align__(16) float W2s[FIN * CLS];
    __shared__ float s2s[CLS], d2s[CLS];
    int t = threadIdx.x;
    for (int i = t; i < FIN * CLS; i += 256) W2s[i] = W2[i];
    if (t < CLS) { s2s[t] = as2[t]; d2s[t] = ad2[t]; }
    __syncthreads();

    int n = blockIdx.x * blockDim.x + t;
    if (n >= NN) return;
    unsigned long long acc[20];
#pragma unroll
    for (int c = 0; c < 20; c++) acc[c] = 0ULL;

    for (int k = 0; k < FIN; k += 4) {
        float4 r4 = *(const float4*)&g_out1[n * FIN + k];
        float rv[4] = {r4.x, r4.y, r4.z, r4.w};
#pragma unroll
        for (int qq = 0; qq < 4; qq++) {
            unsigned long long rp = pk2(rv[qq], rv[qq]);
            const float* wrow = &W2s[(k + qq) * CLS];
#pragma unroll
            for (int c4 = 0; c4 < 10; c4++) {
                ulonglong2 wp = *(const ulonglong2*)&wrow[c4 * 4];
                fma2(acc[c4 * 2 + 0], rp, wp.x);
                fma2(acc[c4 * 2 + 1], rp, wp.y);
            }
        }
    }
    float ls = 0.f, ld = 0.f;
    unsigned int hp[20];
#pragma unroll
    for (int c2 = 0; c2 < 20; c2++) {
        float2 v = up2(acc[c2]);
        hp[c2] = f2h(v.x, v.y);
        ls += v.x * s2s[c2 * 2] + v.y * s2s[c2 * 2 + 1];
        ld += v.x * d2s[c2 * 2] + v.y * d2s[c2 * 2 + 1];
    }
    uint4* dst = (uint4*)&g_h2h[n * CLS];
#pragma unroll
    for (int j = 0; j < 5; j++) {
        uint4 u;
        u.x = hp[j * 4 + 0]; u.y = hp[j * 4 + 1];
        u.z = hp[j * 4 + 2]; u.w = hp[j * 4 + 3];
        dst[j] = u;
    }
    g_als2[n] = ls;
    g_ald2[n] = ld;
}

// ---------------- layer-2 aggregation + bias + log_softmax (8-edge batches) ----------------
__global__ void agg2_kernel(const float* __restrict__ b2, float* __restrict__ out) {
    int gt = blockIdx.x * blockDim.x + threadIdx.x;
    int n = gt >> 5, lane = gt & 31;
    if (n >= NN) return;
    float ald = g_ald2[n];
    int beg = g_rowptr[n], end = g_rowptr[n + 1];
    bool act = lane < 10;
    float4 acc = make_float4(0.f, 0.f, 0.f, 0.f);
    float den = 0.f;
    int i = beg;
    for (; i + 8 <= end; i += 8) {
        int s[8]; float a[8]; uint2 r[8]; float wv[8];
#pragma unroll
        for (int j = 0; j < 8; j++) s[j] = __ldg(&g_csr_src[i + j]);
#pragma unroll
        for (int j = 0; j < 8; j++) a[j] = __ldg(&g_als2[s[j]]);
#pragma unroll
        for (int j = 0; j < 8; j++) {
            r[j] = act ? *(const uint2*)&g_h2h[s[j] * CLS + lane * 4]
                       : make_uint2(0u, 0u);
        }
#pragma unroll
        for (int j = 0; j < 8; j++) { wv[j] = __expf(lrelu(a[j] + ald)); den += wv[j]; }
#pragma unroll
        for (int j = 0; j < 8; j++) {
            float2 p0 = h2f(r[j].x), p1 = h2f(r[j].y);
            acc.x += wv[j] * p0.x; acc.y += wv[j] * p0.y;
            acc.z += wv[j] * p1.x; acc.w += wv[j] * p1.y;
        }
    }
    if (i + 4 <= end) {
        int s[4]; float a[4]; uint2 r[4]; float wv[4];
#pragma unroll
        for (int j = 0; j < 4; j++) s[j] = __ldg(&g_csr_src[i + j]);
#pragma unroll
        for (int j = 0; j < 4; j++) a[j] = __ldg(&g_als2[s[j]]);
#pragma unroll
        for (int j = 0; j < 4; j++) {
            r[j] = act ? *(const uint2*)&g_h2h[s[j] * CLS + lane * 4]
                       : make_uint2(0u, 0u);
        }
#pragma unroll
        for (int j = 0; j < 4; j++) { wv[j] = __expf(lrelu(a[j] + ald)); den += wv[j]; }
#pragma unroll
        for (int j = 0; j < 4; j++) {
            float2 p0 = h2f(r[j].x), p1 = h2f(r[j].y);
            acc.x += wv[j] * p0.x; acc.y += wv[j] * p0.y;
            acc.z += wv[j] * p1.x; acc.w += wv[j] * p1.y;
        }
        i += 4;
    }
    for (; i < end; i++) {
        int s = __ldg(&g_csr_src[i]);
        float wv = __expf(lrelu(__ldg(&g_als2[s]) + ald));
        den += wv;
        if (act) {
            uint2 r = *(const uint2*)&g_h2h[s * CLS + lane * 4];
            float2 p0 = h2f(r.x), p1 = h2f(r.y);
            acc.x += wv * p0.x; acc.y += wv * p0.y;
            acc.z += wv * p1.x; acc.w += wv * p1.y;
        }
    }
    float inv = 1.f / (den + 1e-16f);
    float4 v = make_float4(-1e30f, -1e30f, -1e30f, -1e30f);
    if (act) {
        float4 bb = *(const float4*)&b2[lane * 4];
        v.x = acc.x * inv + bb.x;
        v.y = acc.y * inv + bb.y;
        v.z = acc.z * inv + bb.z;
        v.w = acc.w * inv + bb.w;
    }
    float m = fmaxf(fmaxf(v.x, v.y), fmaxf(v.z, v.w));
#pragma unroll
    for (int o = 16; o > 0; o >>= 1) m = fmaxf(m, __shfl_xor_sync(0xffffffff, m, o));
    float s4 = 0.f;
    if (act)
        s4 = __expf(v.x - m) + __expf(v.y - m) + __expf(v.z - m) + __expf(v.w - m);
#pragma unroll
    for (int o = 16; o > 0; o >>= 1) s4 += __shfl_xor_sync(0xffffffff, s4, o);
    float lse = m + logf(s4);
    if (act) {
        float4 r;
        r.x = v.x - lse; r.y = v.y - lse; r.z = v.z - lse; r.w = v.w - lse;
        *(float4*)&out[n * CLS + lane * 4] = r;
    }
}

// ---------------- launch ----------------
extern "C" void kernel_launch(void* const* d_in, const int* in_sizes, int n_in,
                              void* d_out, int out_size) {
    const float* x   = (const float*)d_in[0];
    const int*   ei  = (const int*)  d_in[1];
    const float* W1  = (const float*)d_in[2];
    const float* as1 = (const float*)d_in[3];
    const float* ad1 = (const float*)d_in[4];
    const float* b1  = (const float*)d_in[5];
    const float* W2  = (const float*)d_in[6];
    const float* as2 = (const float*)d_in[7];
    const float* ad2 = (const float*)d_in[8];
    const float* b2  = (const float*)d_in[9];
    float* out = (float*)d_out;

    cudaStream_t s2;
    cudaEvent_t evA, evB;
    cudaStreamCreateWithFlags(&s2, cudaStreamNonBlocking);
    cudaEventCreateWithFlags(&evA, cudaEventDisableTiming);
    cudaEventCreateWithFlags(&evB, cudaEventDisableTiming);

    cudaEventRecord(evA, 0);
    cudaStreamWaitEvent(s2, evA, 0);

    // branch A: CSR build (parallel scan)
    void* cnt_ptr = nullptr;
    cudaGetSymbolAddress(&cnt_ptr, g_cnt);
    cudaMemsetAsync(cnt_ptr, 0, NN * sizeof(int), s2);
    hist_kernel<<<((TOTE + 7) / 8 + 255) / 256, 256, 0, s2>>>(ei);
    scanA_kernel<<<SCANB, 256, 0, s2>>>();
    scanB_kernel<<<1, 256, 0, s2>>>();
    scanC_kernel<<<SCANB, 256, 0, s2>>>();
    scatter_kernel<<<((TOTE + 7) / 8 + 255) / 256, 256, 0, s2>>>(ei);
    cudaEventRecord(evB, s2);

    // branch B: dense layer 1 (tf32 sync) + fused logits
    gemm1_kernel<<<(NN + 127) / 128, 256>>>(x, W1, as1, ad1);

    cudaStreamWaitEvent(0, evB, 0);

    agg1_kernel<<<(NN * 64 + 255) / 256, 256>>>(b1);
    l2gemm_kernel<<<(NN + 255) / 256, 256>>>(W2, as2, ad2);
    agg2_kernel<<<(NN * 32 + 255) / 256, 256>>>(b2, out);
}